// round 12
// baseline (speedup 1.0000x reference)
#include <cuda_runtime.h>
#include <cuda_bf16.h>
#include <cstdint>

// ---------------------------------------------------------------------------
// GestureBiLSTM: B=1024, T=256, D=63, H=128, O=14
// out = concat(h_f[:, -1], h_b[:, -1]) @ W_fc^T + b_fc
// Key: h_b[:, -1] is ONE lstm step on x[:, T-1] with zero state.
// ---------------------------------------------------------------------------

#define BB   1024
#define TT   256
#define DD   63
#define HH   128
#define G4   512     // 4*H
#define OO   14

typedef unsigned long long u64;

// Scratch (device-global: no allocations allowed in kernel_launch)
__device__ float g_xp[(size_t)BB * TT * G4];   // 512 MB: forward input projection
__device__ float g_Wp[G4 * HH];                // W_hh_f repacked as k-pair float2s
__device__ float g_hf[BB * HH];                // forward last hidden

// --------------------------- helpers ---------------------------------------

__device__ __forceinline__ u64 ffma2(u64 a, u64 b, u64 c) {
    u64 d;
    asm("fma.rn.f32x2 %0, %1, %2, %3;" : "=l"(d) : "l"(a), "l"(b), "l"(c));
    return d;
}
__device__ __forceinline__ float f2lo(u64 v) { return __uint_as_float((unsigned)v); }
__device__ __forceinline__ float f2hi(u64 v) { return __uint_as_float((unsigned)(v >> 32)); }

__device__ __forceinline__ float sigm(float v)  { return 1.0f / (1.0f + __expf(-v)); }
__device__ __forceinline__ float tanhx(float v) { return 2.0f / (1.0f + __expf(-2.0f * v)) - 1.0f; }

// --------------------------- kernel P: pack W_hh ----------------------------
// g_Wp layout: float2 at index [k2*512 + n] = (W_hh[n][2k2], W_hh[n][2k2+1])
__global__ void pack_whh_kernel(const float* __restrict__ Whh) {
    int idx = blockIdx.x * blockDim.x + threadIdx.x;   // 0 .. 64*512-1
    if (idx >= 64 * G4) return;
    int k2 = idx >> 9;
    int n  = idx & 511;
    g_Wp[idx * 2 + 0] = Whh[n * HH + 2 * k2 + 0];
    g_Wp[idx * 2 + 1] = Whh[n * HH + 2 * k2 + 1];
}

// --------------------------- kernel A: xp GEMM ------------------------------
// xp[m][n] = sum_k x[m][k] * W_ih[n][k] + (b_ih[n]+b_hh[n]),  m in [0, B*T)
// 128x128 tile, 8x8 micro, K=63 processed in two 32-chunks (<=48KB smem).
__global__ void __launch_bounds__(256, 2) xp_gemm_kernel(
    const float* __restrict__ x, const float* __restrict__ Wih,
    const float* __restrict__ bih, const float* __restrict__ bhh)
{
    __shared__ float As[32 * 132];   // As[kk][m], padded row 132
    __shared__ float Ws[32 * 132];   // Ws[kk][n]

    const int tid = threadIdx.x;
    const int tx = tid & 15;         // n micro
    const int ty = tid >> 4;         // m micro
    const int m0 = blockIdx.x * 128;
    const int n0 = blockIdx.y * 128;

    float acc[8][8];
#pragma unroll
    for (int i = 0; i < 8; i++)
#pragma unroll
        for (int j = 0; j < 8; j++) acc[i][j] = 0.0f;

    for (int kc = 0; kc < 64; kc += 32) {
        // cooperative load (zero-pad k >= 63)
        for (int idx = tid; idx < 128 * 32; idx += 256) {
            int m  = idx >> 5;
            int kk = idx & 31;
            int k  = kc + kk;
            float av = 0.0f, wv = 0.0f;
            if (k < DD) {
                av = x[(size_t)(m0 + m) * DD + k];
                wv = Wih[(size_t)(n0 + m) * DD + k];
            }
            As[kk * 132 + m] = av;
            Ws[kk * 132 + m] = wv;
        }
        __syncthreads();

#pragma unroll
        for (int kk = 0; kk < 32; kk++) {
            float a[8], b[8];
            *(float4*)&a[0] = *(const float4*)&As[kk * 132 + ty * 8 + 0];
            *(float4*)&a[4] = *(const float4*)&As[kk * 132 + ty * 8 + 4];
            *(float4*)&b[0] = *(const float4*)&Ws[kk * 132 + tx * 8 + 0];
            *(float4*)&b[4] = *(const float4*)&Ws[kk * 132 + tx * 8 + 4];
#pragma unroll
            for (int i = 0; i < 8; i++)
#pragma unroll
                for (int j = 0; j < 8; j++)
                    acc[i][j] = fmaf(a[i], b[j], acc[i][j]);
        }
        __syncthreads();
    }

    float bs[8];
#pragma unroll
    for (int j = 0; j < 8; j++) {
        int n = n0 + tx * 8 + j;
        bs[j] = bih[n] + bhh[n];
    }
#pragma unroll
    for (int i = 0; i < 8; i++) {
        size_t base = (size_t)(m0 + ty * 8 + i) * G4 + n0 + tx * 8;
        float4 v0, v1;
        v0.x = acc[i][0] + bs[0]; v0.y = acc[i][1] + bs[1];
        v0.z = acc[i][2] + bs[2]; v0.w = acc[i][3] + bs[3];
        v1.x = acc[i][4] + bs[4]; v1.y = acc[i][5] + bs[5];
        v1.z = acc[i][6] + bs[6]; v1.w = acc[i][7] + bs[7];
        *(float4*)&g_xp[base]     = v0;
        *(float4*)&g_xp[base + 4] = v1;
    }
}

// --------------------------- kernel B: forward recurrence -------------------
// 128 blocks x 8 batch rows. 256 threads: j = hidden unit (0..127),
// g = batch half (0/1) -> batches g*4 .. g*4+3.
// acc2 holds (even-k partial, odd-k partial) packed f32x2; xp folded into
// the low lane of acc2 at init. FFMA2 doubles fp32 throughput.
__global__ void __launch_bounds__(256, 1) lstm_fwd_kernel()
{
    __shared__ float h_sm[8][HH];

    const int tid = threadIdx.x;
    const int j  = tid & 127;
    const int g  = tid >> 7;          // 0 or 1
    const int g4 = g * 4;
    const int r0 = blockIdx.x * 8;    // batch base

    for (int idx = tid; idx < 8 * HH; idx += 256)
        ((float*)h_sm)[idx] = 0.0f;

    float c[4] = {0.f, 0.f, 0.f, 0.f};

    const float* xpb[4];
#pragma unroll
    for (int b = 0; b < 4; b++)
        xpb[b] = g_xp + (size_t)(r0 + g4 + b) * TT * G4 + j;

    // prefetch t = 0
    float xpv[4][4];
#pragma unroll
    for (int q = 0; q < 4; q++)
#pragma unroll
        for (int b = 0; b < 4; b++)
            xpv[q][b] = xpb[b][q * HH];

    const u64* __restrict__ W2 = (const u64*)g_Wp;   // [k2*512 + n]
    __syncthreads();

    for (int t = 0; t < TT; t++) {
        u64 acc[4][4];
#pragma unroll
        for (int q = 0; q < 4; q++)
#pragma unroll
            for (int b = 0; b < 4; b++)
                acc[q][b] = (u64)__float_as_uint(xpv[q][b]);   // (xp, 0)

        if (t < TT - 1) {
            const int off = (t + 1) * G4;
#pragma unroll
            for (int q = 0; q < 4; q++)
#pragma unroll
                for (int b = 0; b < 4; b++)
                    xpv[q][b] = xpb[b][off + q * HH];
        }

#pragma unroll 4
        for (int k2 = 0; k2 < 64; k2++) {
            u64 w0 = W2[k2 * G4 + j];
            u64 w1 = W2[k2 * G4 + 128 + j];
            u64 w2 = W2[k2 * G4 + 256 + j];
            u64 w3 = W2[k2 * G4 + 384 + j];
            u64 h0 = *(const u64*)&h_sm[g4 + 0][k2 * 2];
            u64 h1 = *(const u64*)&h_sm[g4 + 1][k2 * 2];
            u64 h2 = *(const u64*)&h_sm[g4 + 2][k2 * 2];
            u64 h3 = *(const u64*)&h_sm[g4 + 3][k2 * 2];
            acc[0][0] = ffma2(w0, h0, acc[0][0]);
            acc[0][1] = ffma2(w0, h1, acc[0][1]);
            acc[0][2] = ffma2(w0, h2, acc[0][2]);
            acc[0][3] = ffma2(w0, h3, acc[0][3]);
            acc[1][0] = ffma2(w1, h0, acc[1][0]);
            acc[1][1] = ffma2(w1, h1, acc[1][1]);
            acc[1][2] = ffma2(w1, h2, acc[1][2]);
            acc[1][3] = ffma2(w1, h3, acc[1][3]);
            acc[2][0] = ffma2(w2, h0, acc[2][0]);
            acc[2][1] = ffma2(w2, h1, acc[2][1]);
            acc[2][2] = ffma2(w2, h2, acc[2][2]);
            acc[2][3] = ffma2(w2, h3, acc[2][3]);
            acc[3][0] = ffma2(w3, h0, acc[3][0]);
            acc[3][1] = ffma2(w3, h1, acc[3][1]);
            acc[3][2] = ffma2(w3, h2, acc[3][2]);
            acc[3][3] = ffma2(w3, h3, acc[3][3]);
        }
        __syncthreads();   // all h_sm reads done

#pragma unroll
        for (int b = 0; b < 4; b++) {
            float iv = f2lo(acc[0][b]) + f2hi(acc[0][b]);
            float fv = f2lo(acc[1][b]) + f2hi(acc[1][b]);
            float gv = f2lo(acc[2][b]) + f2hi(acc[2][b]);
            float ov = f2lo(acc[3][b]) + f2hi(acc[3][b]);
            iv = sigm(iv);
            fv = sigm(fv);
            gv = tanhx(gv);
            ov = sigm(ov);
            c[b] = fv * c[b] + iv * gv;
            h_sm[g4 + b][j] = ov * tanhx(c[b]);
        }
        __syncthreads();   // new h visible
    }

#pragma unroll
    for (int b = 0; b < 4; b++)
        g_hf[(size_t)(r0 + g4 + b) * HH + j] = h_sm[g4 + b][j];
}

// --------------------------- kernel C: backward single step + FC ------------
// h_b_last = one LSTM step on x[:, T-1] with zero state:
//   c = sigmoid(i)*tanh(g);  h = sigmoid(o)*tanh(c)    (f gate unused: f*c0=0)
// then out = [h_f, h_b] @ W_fc^T + b_fc
__global__ void __launch_bounds__(128, 4) final_kernel(
    const float* __restrict__ x,   const float* __restrict__ Wihb,
    const float* __restrict__ bihb, const float* __restrict__ bhhb,
    const float* __restrict__ Wfc,  const float* __restrict__ bfc,
    float* __restrict__ out)
{
    __shared__ float xs[8][64];
    __shared__ float hcat[8][2 * HH];

    const int tid = threadIdx.x;      // 0..127
    const int r0 = blockIdx.x * 8;
    const int j = tid;

    for (int idx = tid; idx < 8 * DD; idx += 128) {
        int b = idx / DD, k = idx - b * DD;
        xs[b][k] = x[((size_t)(r0 + b) * TT + (TT - 1)) * DD + k];
    }
#pragma unroll
    for (int b = 0; b < 8; b++)
        hcat[b][j] = g_hf[(size_t)(r0 + b) * HH + j];
    __syncthreads();

    float ai[8], ag[8], ao[8];
    const float bi = bihb[j]       + bhhb[j];
    const float bg = bihb[256 + j] + bhhb[256 + j];
    const float bo = bihb[384 + j] + bhhb[384 + j];
#pragma unroll
    for (int b = 0; b < 8; b++) { ai[b] = bi; ag[b] = bg; ao[b] = bo; }

    for (int k = 0; k < DD; k++) {
        float wi = Wihb[(size_t)j * DD + k];
        float wg = Wihb[(size_t)(256 + j) * DD + k];
        float wo = Wihb[(size_t)(384 + j) * DD + k];
#pragma unroll
        for (int b = 0; b < 8; b++) {
            float xv = xs[b][k];
            ai[b] = fmaf(wi, xv, ai[b]);
            ag[b] = fmaf(wg, xv, ag[b]);
            ao[b] = fmaf(wo, xv, ao[b]);
        }
    }
#pragma unroll
    for (int b = 0; b < 8; b++) {
        float cc = sigm(ai[b]) * tanhx(ag[b]);
        hcat[b][HH + j] = sigm(ao[b]) * tanhx(cc);
    }
    __syncthreads();

    if (tid < 8 * OO) {
        int b = tid / OO, o = tid - b * OO;
        float s = bfc[o];
        const float* wrow = Wfc + (size_t)o * (2 * HH);
        for (int m = 0; m < 2 * HH; m++)
            s = fmaf(hcat[b][m], wrow[m], s);
        out[(size_t)(r0 + b) * OO + o] = s;
    }
}

// --------------------------- launch ----------------------------------------
extern "C" void kernel_launch(void* const* d_in, const int* in_sizes, int n_in,
                              void* d_out, int out_size)
{
    const float* x    = (const float*)d_in[0];
    const float* Wihf = (const float*)d_in[1];
    const float* Whhf = (const float*)d_in[2];
    const float* bihf = (const float*)d_in[3];
    const float* bhhf = (const float*)d_in[4];
    const float* Wihb = (const float*)d_in[5];
    // d_in[6] = W_hh_b: unused — backward direction only contributes its first
    // step (zero initial state), so its W_hh term vanishes.
    const float* bihb = (const float*)d_in[7];
    const float* bhhb = (const float*)d_in[8];
    const float* Wfc  = (const float*)d_in[9];
    const float* bfc  = (const float*)d_in[10];
    float* out = (float*)d_out;

    (void)in_sizes; (void)n_in; (void)out_size;

    // P: repack W_hh_f into k-pair float2 layout for coalesced FFMA2 loads
    pack_whh_kernel<<<128, 256>>>(Whhf);

    // A: xp = x @ W_ih_f^T + (b_ih_f + b_hh_f)   for all B*T rows
    dim3 gA((BB * TT) / 128, G4 / 128);
    xp_gemm_kernel<<<gA, 256>>>(x, Wihf, bihf, bhhf);

    // B: forward recurrence (persistent, batch-parallel, 256 steps)
    lstm_fwd_kernel<<<BB / 8, 256>>>();

    // C: backward single step + concat + final FC
    final_kernel<<<BB / 8, 128>>>(x, Wihb, bihb, bhhb, Wfc, bfc, out);
}

// round 14
// speedup vs baseline: 1.5652x; 1.5652x over previous
#include <cuda_runtime.h>
#include <cuda_bf16.h>
#include <cstdint>

// ---------------------------------------------------------------------------
// GestureBiLSTM: B=1024, T=256, D=63, H=128, O=14
// out = concat(h_f[:, -1], h_b[:, -1]) @ W_fc^T + b_fc
// h_b[:, -1] is ONE lstm step on x[:, T-1] with zero state.
//
// R12: (a) lstm_fwd weights become SM-resident: gates i,f,g in 192KB smem,
//          gate o in 64 u64 registers/thread. No LDG in the recurrence loop.
//      (b) xp GEMM converted to fma.rn.f32x2 (output-column-pair packing).
// ---------------------------------------------------------------------------

#define BB   1024
#define TT   256
#define DD   63
#define HH   128
#define G4   512     // 4*H
#define OO   14

typedef unsigned long long u64;

// Scratch (device-global: no allocations allowed in kernel_launch)
__device__ float g_xp[(size_t)BB * TT * G4];   // 512 MB: forward input projection
__device__ float g_Wp[G4 * HH];                // W_hh_f repacked as k-pair float2s
__device__ float g_hf[BB * HH];                // forward last hidden

// --------------------------- helpers ---------------------------------------

__device__ __forceinline__ u64 ffma2(u64 a, u64 b, u64 c) {
    u64 d;
    asm("fma.rn.f32x2 %0, %1, %2, %3;" : "=l"(d) : "l"(a), "l"(b), "l"(c));
    return d;
}
__device__ __forceinline__ u64 dup2(float v) {
    u64 r;
    asm("mov.b64 %0, {%1, %1};" : "=l"(r) : "f"(v));
    return r;
}
__device__ __forceinline__ u64 pack2(float lo, float hi) {
    u64 r;
    asm("mov.b64 %0, {%1, %2};" : "=l"(r) : "f"(lo), "f"(hi));
    return r;
}
__device__ __forceinline__ float f2lo(u64 v) { return __uint_as_float((unsigned)v); }
__device__ __forceinline__ float f2hi(u64 v) { return __uint_as_float((unsigned)(v >> 32)); }

__device__ __forceinline__ float sigm(float v)  { return 1.0f / (1.0f + __expf(-v)); }
__device__ __forceinline__ float tanhx(float v) { return 2.0f / (1.0f + __expf(-2.0f * v)) - 1.0f; }

// --------------------------- kernel P: pack W_hh ----------------------------
// g_Wp layout: float2 at index [k2*512 + n] = (W_hh[n][2k2], W_hh[n][2k2+1])
__global__ void pack_whh_kernel(const float* __restrict__ Whh) {
    int idx = blockIdx.x * blockDim.x + threadIdx.x;   // 0 .. 64*512-1
    if (idx >= 64 * G4) return;
    int k2 = idx >> 9;
    int n  = idx & 511;
    g_Wp[idx * 2 + 0] = Whh[n * HH + 2 * k2 + 0];
    g_Wp[idx * 2 + 1] = Whh[n * HH + 2 * k2 + 1];
}

// --------------------------- kernel A: xp GEMM (FFMA2) ----------------------
// xp[m][n] = sum_k x[m][k] * W_ih[n][k] + (b_ih[n]+b_hh[n]),  m in [0, B*T)
// 128x128 tile, 8x8 micro, K=63 in two 32-chunks.
// Accumulators pack adjacent OUTPUT COLUMNS as f32x2 (exact per-lane fp32).
__global__ void __launch_bounds__(256, 1) xp_gemm_kernel(
    const float* __restrict__ x, const float* __restrict__ Wih,
    const float* __restrict__ bih, const float* __restrict__ bhh)
{
    __shared__ float As[32 * 132];   // As[kk][m], padded row 132
    __shared__ float Ws[32 * 132];   // Ws[kk][n]

    const int tid = threadIdx.x;
    const int tx = tid & 15;         // n micro
    const int ty = tid >> 4;         // m micro
    const int m0 = blockIdx.x * 128;
    const int n0 = blockIdx.y * 128;

    // bias pairs; acc initialized with bias (order change is within fp32 noise)
    u64 acc2[8][4];
    {
        u64 bp[4];
#pragma unroll
        for (int j2 = 0; j2 < 4; j2++) {
            int n = n0 + tx * 8 + 2 * j2;
            bp[j2] = pack2(bih[n] + bhh[n], bih[n + 1] + bhh[n + 1]);
        }
#pragma unroll
        for (int i = 0; i < 8; i++)
#pragma unroll
            for (int j2 = 0; j2 < 4; j2++) acc2[i][j2] = bp[j2];
    }

    for (int kc = 0; kc < 64; kc += 32) {
        // cooperative load (zero-pad k >= 63)
        for (int idx = tid; idx < 128 * 32; idx += 256) {
            int m  = idx >> 5;
            int kk = idx & 31;
            int k  = kc + kk;
            float av = 0.0f, wv = 0.0f;
            if (k < DD) {
                av = x[(size_t)(m0 + m) * DD + k];
                wv = Wih[(size_t)(n0 + m) * DD + k];
            }
            As[kk * 132 + m] = av;
            Ws[kk * 132 + m] = wv;
        }
        __syncthreads();

#pragma unroll
        for (int kk = 0; kk < 32; kk++) {
            float a[8];
            *(float4*)&a[0] = *(const float4*)&As[kk * 132 + ty * 8 + 0];
            *(float4*)&a[4] = *(const float4*)&As[kk * 132 + ty * 8 + 4];
            ulonglong2 bq0 = *(const ulonglong2*)&Ws[kk * 132 + tx * 8 + 0];
            ulonglong2 bq1 = *(const ulonglong2*)&Ws[kk * 132 + tx * 8 + 4];
            u64 b2[4] = {bq0.x, bq0.y, bq1.x, bq1.y};
#pragma unroll
            for (int i = 0; i < 8; i++) {
                u64 a2 = dup2(a[i]);
#pragma unroll
                for (int j2 = 0; j2 < 4; j2++)
                    acc2[i][j2] = ffma2(a2, b2[j2], acc2[i][j2]);
            }
        }
        __syncthreads();
    }

#pragma unroll
    for (int i = 0; i < 8; i++) {
        size_t base = (size_t)(m0 + ty * 8 + i) * G4 + n0 + tx * 8;
        float4 v0, v1;
        v0.x = f2lo(acc2[i][0]); v0.y = f2hi(acc2[i][0]);
        v0.z = f2lo(acc2[i][1]); v0.w = f2hi(acc2[i][1]);
        v1.x = f2lo(acc2[i][2]); v1.y = f2hi(acc2[i][2]);
        v1.z = f2lo(acc2[i][3]); v1.w = f2hi(acc2[i][3]);
        *(float4*)&g_xp[base]     = v0;
        *(float4*)&g_xp[base + 4] = v1;
    }
}

// --------------------------- kernel B: forward recurrence -------------------
// 128 blocks x 8 batch rows. 256 threads: j = hidden unit (0..127),
// g = batch half (0/1) -> batches g*4 .. g*4+3.
// Weights for gates i,f,g live in 192KB dynamic smem (k-quad float4 layout);
// gate-o weights live in 64 u64 registers per thread. Zero LDG in mainloop.
__global__ void __launch_bounds__(256, 1) lstm_fwd_kernel()
{
    extern __shared__ float4 wsq[];        // [32*384] float4: wsq[k4*384 + gate*128 + j]
    __shared__ float h_sm[8][HH];          // static 4KB

    const int tid = threadIdx.x;
    const int j  = tid & 127;
    const int g  = tid >> 7;          // 0 or 1 (warp-uniform)
    const int g4 = g * 4;
    const int r0 = blockIdx.x * 8;    // batch base

    const u64* __restrict__ W2 = (const u64*)g_Wp;   // [k2*512 + n]

    // Fill smem weights for gates 0..2 (i, f, g), k-quad packed.
    for (int idx = tid; idx < 32 * 384; idx += 256) {
        int k4  = idx / 384;
        int rem = idx - k4 * 384;              // gate*128 + j, gate in {0,1,2}
        ulonglong2 v;
        v.x = W2[(2 * k4 + 0) * G4 + rem];     // (W[n][4k4],   W[n][4k4+1])
        v.y = W2[(2 * k4 + 1) * G4 + rem];     // (W[n][4k4+2], W[n][4k4+3])
        *(ulonglong2*)&wsq[idx] = v;
    }

    // Gate-o weight row in registers (statically indexed: loop fully unrolled).
    u64 wreg[64];
#pragma unroll
    for (int k2 = 0; k2 < 64; k2++)
        wreg[k2] = W2[k2 * G4 + 384 + j];

    for (int idx = tid; idx < 8 * HH; idx += 256)
        ((float*)h_sm)[idx] = 0.0f;

    float c[4] = {0.f, 0.f, 0.f, 0.f};

    const float* xpb[4];
#pragma unroll
    for (int b = 0; b < 4; b++)
        xpb[b] = g_xp + (size_t)(r0 + g4 + b) * TT * G4 + j;

    // prefetch t = 0
    float xpv[4][4];
#pragma unroll
    for (int q = 0; q < 4; q++)
#pragma unroll
        for (int b = 0; b < 4; b++)
            xpv[q][b] = xpb[b][q * HH];

    __syncthreads();

    for (int t = 0; t < TT; t++) {
        u64 acc[4][4];
#pragma unroll
        for (int q = 0; q < 4; q++)
#pragma unroll
            for (int b = 0; b < 4; b++)
                acc[q][b] = (u64)__float_as_uint(xpv[q][b]);   // (xp, 0)

        if (t < TT - 1) {
            const int off = (t + 1) * G4;
#pragma unroll
            for (int q = 0; q < 4; q++)
#pragma unroll
                for (int b = 0; b < 4; b++)
                    xpv[q][b] = xpb[b][off + q * HH];
        }

#pragma unroll
        for (int k4 = 0; k4 < 32; k4++) {
            ulonglong2 wi = *(const ulonglong2*)&wsq[k4 * 384 + j];
            ulonglong2 wf = *(const ulonglong2*)&wsq[k4 * 384 + 128 + j];
            ulonglong2 wg = *(const ulonglong2*)&wsq[k4 * 384 + 256 + j];
            u64 wo0 = wreg[2 * k4 + 0];
            u64 wo1 = wreg[2 * k4 + 1];
            ulonglong2 h0 = *(const ulonglong2*)&h_sm[g4 + 0][k4 * 4];
            ulonglong2 h1 = *(const ulonglong2*)&h_sm[g4 + 1][k4 * 4];
            ulonglong2 h2 = *(const ulonglong2*)&h_sm[g4 + 2][k4 * 4];
            ulonglong2 h3 = *(const ulonglong2*)&h_sm[g4 + 3][k4 * 4];

            acc[0][0] = ffma2(wi.x, h0.x, acc[0][0]);
            acc[0][1] = ffma2(wi.x, h1.x, acc[0][1]);
            acc[0][2] = ffma2(wi.x, h2.x, acc[0][2]);
            acc[0][3] = ffma2(wi.x, h3.x, acc[0][3]);
            acc[1][0] = ffma2(wf.x, h0.x, acc[1][0]);
            acc[1][1] = ffma2(wf.x, h1.x, acc[1][1]);
            acc[1][2] = ffma2(wf.x, h2.x, acc[1][2]);
            acc[1][3] = ffma2(wf.x, h3.x, acc[1][3]);
            acc[2][0] = ffma2(wg.x, h0.x, acc[2][0]);
            acc[2][1] = ffma2(wg.x, h1.x, acc[2][1]);
            acc[2][2] = ffma2(wg.x, h2.x, acc[2][2]);
            acc[2][3] = ffma2(wg.x, h3.x, acc[2][3]);
            acc[3][0] = ffma2(wo0,  h0.x, acc[3][0]);
            acc[3][1] = ffma2(wo0,  h1.x, acc[3][1]);
            acc[3][2] = ffma2(wo0,  h2.x, acc[3][2]);
            acc[3][3] = ffma2(wo0,  h3.x, acc[3][3]);

            acc[0][0] = ffma2(wi.y, h0.y, acc[0][0]);
            acc[0][1] = ffma2(wi.y, h1.y, acc[0][1]);
            acc[0][2] = ffma2(wi.y, h2.y, acc[0][2]);
            acc[0][3] = ffma2(wi.y, h3.y, acc[0][3]);
            acc[1][0] = ffma2(wf.y, h0.y, acc[1][0]);
            acc[1][1] = ffma2(wf.y, h1.y, acc[1][1]);
            acc[1][2] = ffma2(wf.y, h2.y, acc[1][2]);
            acc[1][3] = ffma2(wf.y, h3.y, acc[1][3]);
            acc[2][0] = ffma2(wg.y, h0.y, acc[2][0]);
            acc[2][1] = ffma2(wg.y, h1.y, acc[2][1]);
            acc[2][2] = ffma2(wg.y, h2.y, acc[2][2]);
            acc[2][3] = ffma2(wg.y, h3.y, acc[2][3]);
            acc[3][0] = ffma2(wo1,  h0.y, acc[3][0]);
            acc[3][1] = ffma2(wo1,  h1.y, acc[3][1]);
            acc[3][2] = ffma2(wo1,  h2.y, acc[3][2]);
            acc[3][3] = ffma2(wo1,  h3.y, acc[3][3]);
        }
        __syncthreads();   // all h_sm reads done

#pragma unroll
        for (int b = 0; b < 4; b++) {
            float iv = f2lo(acc[0][b]) + f2hi(acc[0][b]);
            float fv = f2lo(acc[1][b]) + f2hi(acc[1][b]);
            float gv = f2lo(acc[2][b]) + f2hi(acc[2][b]);
            float ov = f2lo(acc[3][b]) + f2hi(acc[3][b]);
            iv = sigm(iv);
            fv = sigm(fv);
            gv = tanhx(gv);
            ov = sigm(ov);
            c[b] = fv * c[b] + iv * gv;
            h_sm[g4 + b][j] = ov * tanhx(c[b]);
        }
        __syncthreads();   // new h visible
    }

#pragma unroll
    for (int b = 0; b < 4; b++)
        g_hf[(size_t)(r0 + g4 + b) * HH + j] = h_sm[g4 + b][j];
}

// --------------------------- kernel C: backward single step + FC ------------
// h_b_last = one LSTM step on x[:, T-1] with zero state:
//   c = sigmoid(i)*tanh(g);  h = sigmoid(o)*tanh(c)    (f gate unused: f*c0=0)
// then out = [h_f, h_b] @ W_fc^T + b_fc
__global__ void __launch_bounds__(128, 4) final_kernel(
    const float* __restrict__ x,   const float* __restrict__ Wihb,
    const float* __restrict__ bihb, const float* __restrict__ bhhb,
    const float* __restrict__ Wfc,  const float* __restrict__ bfc,
    float* __restrict__ out)
{
    __shared__ float xs[8][64];
    __shared__ float hcat[8][2 * HH];

    const int tid = threadIdx.x;      // 0..127
    const int r0 = blockIdx.x * 8;
    const int j = tid;

    for (int idx = tid; idx < 8 * DD; idx += 128) {
        int b = idx / DD, k = idx - b * DD;
        xs[b][k] = x[((size_t)(r0 + b) * TT + (TT - 1)) * DD + k];
    }
#pragma unroll
    for (int b = 0; b < 8; b++)
        hcat[b][j] = g_hf[(size_t)(r0 + b) * HH + j];
    __syncthreads();

    float ai[8], ag[8], ao[8];
    const float bi = bihb[j]       + bhhb[j];
    const float bg = bihb[256 + j] + bhhb[256 + j];
    const float bo = bihb[384 + j] + bhhb[384 + j];
#pragma unroll
    for (int b = 0; b < 8; b++) { ai[b] = bi; ag[b] = bg; ao[b] = bo; }

    for (int k = 0; k < DD; k++) {
        float wi = Wihb[(size_t)j * DD + k];
        float wg = Wihb[(size_t)(256 + j) * DD + k];
        float wo = Wihb[(size_t)(384 + j) * DD + k];
#pragma unroll
        for (int b = 0; b < 8; b++) {
            float xv = xs[b][k];
            ai[b] = fmaf(wi, xv, ai[b]);
            ag[b] = fmaf(wg, xv, ag[b]);
            ao[b] = fmaf(wo, xv, ao[b]);
        }
    }
#pragma unroll
    for (int b = 0; b < 8; b++) {
        float cc = sigm(ai[b]) * tanhx(ag[b]);
        hcat[b][HH + j] = sigm(ao[b]) * tanhx(cc);
    }
    __syncthreads();

    if (tid < 8 * OO) {
        int b = tid / OO, o = tid - b * OO;
        float s = bfc[o];
        const float* wrow = Wfc + (size_t)o * (2 * HH);
        for (int m = 0; m < 2 * HH; m++)
            s = fmaf(hcat[b][m], wrow[m], s);
        out[(size_t)(r0 + b) * OO + o] = s;
    }
}

// --------------------------- launch ----------------------------------------
extern "C" void kernel_launch(void* const* d_in, const int* in_sizes, int n_in,
                              void* d_out, int out_size)
{
    const float* x    = (const float*)d_in[0];
    const float* Wihf = (const float*)d_in[1];
    const float* Whhf = (const float*)d_in[2];
    const float* bihf = (const float*)d_in[3];
    const float* bhhf = (const float*)d_in[4];
    const float* Wihb = (const float*)d_in[5];
    // d_in[6] = W_hh_b: unused — backward direction only contributes its first
    // step (zero initial state), so its W_hh term vanishes.
    const float* bihb = (const float*)d_in[7];
    const float* bhhb = (const float*)d_in[8];
    const float* Wfc  = (const float*)d_in[9];
    const float* bfc  = (const float*)d_in[10];
    float* out = (float*)d_out;

    (void)in_sizes; (void)n_in; (void)out_size;

    // 192 KB dynamic smem for the recurrence weights (gates i,f,g).
    static const int LSTM_SMEM = 32 * 384 * (int)sizeof(float4);   // 196608
    cudaFuncSetAttribute(lstm_fwd_kernel,
                         cudaFuncAttributeMaxDynamicSharedMemorySize, LSTM_SMEM);

    // P: repack W_hh_f into k-pair float2 layout
    pack_whh_kernel<<<128, 256>>>(Whhf);

    // A: xp = x @ W_ih_f^T + (b_ih_f + b_hh_f)   for all B*T rows (FFMA2)
    dim3 gA((BB * TT) / 128, G4 / 128);
    xp_gemm_kernel<<<gA, 256>>>(x, Wihf, bihf, bhhf);

    // B: forward recurrence (persistent, batch-parallel, 256 steps)
    lstm_fwd_kernel<<<BB / 8, 256, LSTM_SMEM>>>();

    // C: backward single step + concat + final FC
    final_kernel<<<BB / 8, 128>>>(x, Wihb, bihb, bhhb, Wfc, bfc, out);
}